// round 2
// baseline (speedup 1.0000x reference)
#include <cuda_runtime.h>
#include <math.h>

#define HOPSZ 512
#define MAX_NHAR 128
#define N_MAX_WIN 4410
#define NWPAD 4416
#define TWO_PI_D 6.283185307179586476925286766559
#define INV_TWO_PI_D 0.15915494309189533576888376337251

__global__ __launch_bounds__(256) void czt_goertzel_kernel(
    const float* __restrict__ x,
    const float* __restrict__ f0g,
    float* __restrict__ out,
    int T, int nframes)
{
    __shared__ __align__(16) float xw[NWPAD];
    __shared__ float red_r[256], red_i[256];
    __shared__ double om_s[32];
    __shared__ float tchi_s[32], tclo_s[32], c1_s[32], clo_s[32], sn_s[32];

    const int frame = blockIdx.x;
    const int kbase = blockIdx.y * 32;
    const int tid = threadIdx.x;

    // per-frame scalars (match reference fp64 arithmetic exactly)
    double f0 = (double)f0g[frame];
    if (f0 < 40.0) f0 = 40.0;
    const double sr_over_f0 = 44100.0 / f0;
    int nhar = (int)floor(sr_over_f0 * 0.5);          // == floor((SR/f0)/2)
    if (nhar > MAX_NHAR) nhar = MAX_NHAR;
    int winsize = 2 * (int)rint(sr_over_f0 * 2.0);    // == round(SR/f0*4/2)*2, half-even
    if (winsize > N_MAX_WIN) winsize = N_MAX_WIN;
    const double theta = (TWO_PI_D * f0) / 44100.0;   // == 2.0*pi*f0/SR

    // k-chunks entirely beyond nhar: write zeros and leave (uniform branch)
    if (kbase >= nhar) {
        if (tid < 32) {
            out[(kbase + tid) * nframes + frame] = 0.0f;
            out[(MAX_NHAR + kbase + tid) * nframes + frame] = 0.0f;
        }
        return;
    }

    // ---- phase 1: windowed frame -> smem, zero-padded to multiple of 4 ----
    const int base = frame * HOPSZ - (winsize >> 1);
    const float invn = 1.0f / (float)winsize;
    const int wsz4 = (winsize + 3) & ~3;
    for (int j = tid; j < wsz4; j += 256) {
        float v = 0.0f;
        if (j < winsize) {
            int gi = base + j;
            float xv = (gi >= 0 && gi < T) ? x[gi] : 0.0f;
            float a = 6.28318530717958647692f * ((float)j * invn);
            float w = 0.42f - 0.5f * __cosf(a) + 0.08f * __cosf(2.0f * a);
            v = xv * w;
        }
        xw[j] = v;
    }

    // ---- per-harmonic constants (fp64 once per k, shared) ----
    if (tid < 32) {
        int k = kbase + tid;
        double om = theta * (double)(k + 1);
        double cd = cos(om);
        double tc = 2.0 * cd;
        float th = (float)tc;
        om_s[tid]   = om;
        tchi_s[tid] = th;
        tclo_s[tid] = (float)(tc - (double)th);
        float c1 = (float)cd;
        c1_s[tid]  = c1;
        clo_s[tid] = (float)(cd - (double)c1);
        double s2d = 1.0 - cd * cd;
        sn_s[tid]  = (float)sqrt(s2d > 0.0 ? s2d : 0.0);
    }
    __syncthreads();

    // ---- phase 2: Goertzel, thread = (harmonic kl, window segment seg) ----
    const int kl = tid & 31;
    const int seg = tid >> 5;          // warp-uniform
    const int k = kbase + kl;

    float accr = 0.0f, acci = 0.0f;

    if (k < nhar) {
        const double om = om_s[kl];
        const float tchi = tchi_s[kl], tclo = tclo_s[kl];
        const float c1 = c1_s[kl], clo = clo_s[kl], sn = sn_s[kl];

        int Lc = (((winsize + 7) >> 3) + 3) & ~3;    // per-seg span, mult of 4
        int a0 = seg * Lc;
        int b0 = a0 + Lc; if (b0 > wsz4) b0 = wsz4;

        for (int a = a0; a < b0; a += 128) {         // resync sub-segments
            int b = a + 128; if (b > b0) b = b0;
            float s1 = 0.0f, s2 = 0.0f;
            const float4* p = (const float4*)(xw + a);
            int n4 = (b - a) >> 2;
            #pragma unroll 4
            for (int i = 0; i < n4; ++i) {
                float4 xv = p[i];
                float A = fmaf(tchi, s1, fmaf(tclo, s1, xv.x - s2));
                float B = fmaf(tchi, A,  fmaf(tclo, A,  xv.y - s1));
                float C = fmaf(tchi, B,  fmaf(tclo, B,  xv.z - A));
                float D = fmaf(tchi, C,  fmaf(tclo, C,  xv.w - B));
                s2 = C; s1 = D;
            }
            // sub-segment DFT value, rotated by exact e^{-i om (b-1)}
            float xr = fmaf(-c1, s2, s1);
            xr = fmaf(-clo, s2, xr);
            float xi = s2 * sn;
            double ph = om * (double)(b - 1);
            ph -= TWO_PI_D * rint(ph * INV_TWO_PI_D);
            float cp, sp;
            __sincosf((float)ph, &sp, &cp);
            accr += xr * cp + xi * sp;
            acci += xi * cp - xr * sp;
        }
    }

    red_r[tid] = accr;
    red_i[tid] = acci;
    __syncthreads();

    // ---- epilogue: combine 8 segments per harmonic, scale, write ----
    if (tid < 32) {
        float rr = 0.0f, ri = 0.0f;
        #pragma unroll
        for (int s = 0; s < 8; ++s) { rr += red_r[s * 32 + tid]; ri += red_i[s * 32 + tid]; }
        float ampl = 0.0f, phs = 0.0f;
        int kk = kbase + tid;
        if (kk < nhar) {
            float scale = (float)(2.381 / (double)((winsize >> 1) + 1));
            float yr = rr * scale, yi = ri * scale;
            ampl = sqrtf(yr * yr + yi * yi);
            phs = atan2f(yi, yr);
        }
        out[kk * nframes + frame] = ampl;
        out[(MAX_NHAR + kk) * nframes + frame] = phs;
    }
}

extern "C" void kernel_launch(void* const* d_in, const int* in_sizes, int n_in,
                              void* d_out, int out_size) {
    const float* x  = (const float*)d_in[0];
    const float* f0 = (const float*)d_in[1];
    float* out = (float*)d_out;
    int T = in_sizes[0];
    int nframes = in_sizes[1];
    dim3 grid(nframes, 4);
    czt_goertzel_kernel<<<grid, 256>>>(x, f0, out, T, nframes);
}

// round 3
// speedup vs baseline: 1.1542x; 1.1542x over previous
#include <cuda_runtime.h>
#include <math.h>

#define HOPSZ 512
#define MAX_NHAR 128
#define NWPAD 4416              // >= max winsize 4410, multiple of 8
#define TWO_PI_D 6.283185307179586476925286766559
#define INV_TWO_PI_D 0.15915494309189533576888376337251

__global__ __launch_bounds__(256) void czt_blocktwiddle_kernel(
    const float* __restrict__ x,
    const float* __restrict__ f0g,
    float* __restrict__ out,
    int T, int nframes)
{
    __shared__ __align__(16) float xw[NWPAD];
    __shared__ float red_r[256], red_i[256];

    const int frame = blockIdx.x;
    const int tid = threadIdx.x;

    // per-frame scalars (fp64, matching reference semantics)
    double f0 = (double)f0g[frame];
    if (f0 < 40.0) f0 = 40.0;
    const double sr_over_f0 = 44100.0 / f0;
    int nhar = (int)floor(sr_over_f0 * 0.5);
    if (nhar > MAX_NHAR) nhar = MAX_NHAR;
    int winsize = 2 * (int)rint(sr_over_f0 * 2.0);    // round-half-even * 2
    if (winsize > 4410) winsize = 4410;
    const double theta = (TWO_PI_D * f0) / 44100.0;

    // ---- phase 1: windowed frame -> smem, zero-padded to multiple of 8 ----
    const int base = frame * HOPSZ - (winsize >> 1);
    const float invn = 1.0f / (float)winsize;
    const int wsz8 = (winsize + 7) & ~7;
    for (int j = tid; j < wsz8; j += 256) {
        float v = 0.0f;
        if (j < winsize) {
            int gi = base + j;
            float xv = (gi >= 0 && gi < T) ? x[gi] : 0.0f;
            float a = 6.28318530717958647692f * ((float)j * invn);
            float w = 0.42f - 0.5f * __cosf(a) + 0.08f * __cosf(2.0f * a);
            v = xv * w;
        }
        xw[j] = v;
    }
    __syncthreads();

    // ---- phase 2: thread = (harmonic k, half-segment) ----
    const int k = tid & (MAX_NHAR - 1);
    const int seg = tid >> 7;                 // 0 or 1

    float accr = 0.0f, acci = 0.0f;

    if (k < nhar) {
        const double om = theta * (double)(k + 1);    // <= ~pi

        // per-thread twiddles u_d = e^{-i om d}, d=0..7  (cc = cos, ns = -sin)
        float cc1, cc2, cc3, cc4, cc5, cc6, cc7;
        float ns1, ns2, ns3, ns4, ns5, ns6, ns7;
        {
            float s, c;
            double p;
            p = om;       p -= TWO_PI_D * rint(p * INV_TWO_PI_D); __sincosf((float)p, &s, &c); cc1 = c; ns1 = -s;
            p = om * 2.0; p -= TWO_PI_D * rint(p * INV_TWO_PI_D); __sincosf((float)p, &s, &c); cc2 = c; ns2 = -s;
            p = om * 3.0; p -= TWO_PI_D * rint(p * INV_TWO_PI_D); __sincosf((float)p, &s, &c); cc3 = c; ns3 = -s;
            p = om * 4.0; p -= TWO_PI_D * rint(p * INV_TWO_PI_D); __sincosf((float)p, &s, &c); cc4 = c; ns4 = -s;
            p = om * 5.0; p -= TWO_PI_D * rint(p * INV_TWO_PI_D); __sincosf((float)p, &s, &c); cc5 = c; ns5 = -s;
            p = om * 6.0; p -= TWO_PI_D * rint(p * INV_TWO_PI_D); __sincosf((float)p, &s, &c); cc6 = c; ns6 = -s;
            p = om * 7.0; p -= TWO_PI_D * rint(p * INV_TWO_PI_D); __sincosf((float)p, &s, &c); cc7 = c; ns7 = -s;
        }
        // block rotor W8 = e^{-i 8 om}
        float w8r, w8i, nw8i;
        {
            double p = om * 8.0; p -= TWO_PI_D * rint(p * INV_TWO_PI_D);
            float s, c; __sincosf((float)p, &s, &c);
            w8r = c; w8i = -s; nw8i = s;
        }

        // segment range: mult-of-8 split of [0, wsz8)
        const int Lc = ((wsz8 >> 1) + 7) & ~7;
        const int a0 = seg ? Lc : 0;
        const int b0 = seg ? wsz8 : Lc;

        for (int a2 = a0; a2 < b0; a2 += 128) {
            // exact rotor resync: Wcur = e^{-i om a2}
            double ph = om * (double)a2;
            ph -= TWO_PI_D * rint(ph * INV_TWO_PI_D);
            float sp, cp; __sincosf((float)ph, &sp, &cp);
            float wr = cp, wi = -sp, nwi = sp;
            int bend = a2 + 128; if (bend > b0) bend = b0;
            #pragma unroll 2
            for (int j0 = a2; j0 < bend; j0 += 8) {
                float4 xa = *(const float4*)(xw + j0);
                float4 xb = *(const float4*)(xw + j0 + 4);
                // partials over the 8-sample block (independent FMA chains)
                float pra = xa.x;                       // cc0 = 1
                pra = fmaf(xa.y, cc1, pra);
                pra = fmaf(xa.z, cc2, pra);
                pra = fmaf(xa.w, cc3, pra);
                float prb = xb.x * cc4;
                prb = fmaf(xb.y, cc5, prb);
                prb = fmaf(xb.z, cc6, prb);
                prb = fmaf(xb.w, cc7, prb);
                float pia = xa.y * ns1;                 // ns0 = 0
                pia = fmaf(xa.z, ns2, pia);
                pia = fmaf(xa.w, ns3, pia);
                float pib = xb.x * ns4;
                pib = fmaf(xb.y, ns5, pib);
                pib = fmaf(xb.z, ns6, pib);
                pib = fmaf(xb.w, ns7, pib);
                float pr = pra + prb;
                float pi = pia + pib;
                // fold into accumulator: acc += (pr + i*pi) * (wr + i*wi)
                accr = fmaf(pi, nwi, accr); accr = fmaf(pr, wr, accr);
                acci = fmaf(pi, wr,  acci); acci = fmaf(pr, wi, acci);
                // advance rotor: W *= W8
                float t1 = wi * nw8i;
                float nr = fmaf(wr, w8r, t1);
                float t2 = wi * w8r;
                float ni = fmaf(wr, w8i, t2);
                wr = nr; wi = ni; nwi = -ni;
            }
        }
    }

    red_r[tid] = accr;
    red_i[tid] = acci;
    __syncthreads();

    // ---- epilogue: combine 2 segments, scale, write ampl + phase ----
    if (tid < MAX_NHAR) {
        float ampl = 0.0f, phs = 0.0f;
        if (tid < nhar) {
            float rr = red_r[tid] + red_r[tid + 128];
            float ri = red_i[tid] + red_i[tid + 128];
            float scale = (float)(2.381 / (double)((winsize >> 1) + 1));
            float yr = rr * scale, yi = ri * scale;
            ampl = sqrtf(yr * yr + yi * yi);
            phs = atan2f(yi, yr);
        }
        out[tid * nframes + frame] = ampl;
        out[(MAX_NHAR + tid) * nframes + frame] = phs;
    }
}

extern "C" void kernel_launch(void* const* d_in, const int* in_sizes, int n_in,
                              void* d_out, int out_size) {
    const float* x  = (const float*)d_in[0];
    const float* f0 = (const float*)d_in[1];
    float* out = (float*)d_out;
    int T = in_sizes[0];
    int nframes = in_sizes[1];
    czt_blocktwiddle_kernel<<<nframes, 256>>>(x, f0, out, T, nframes);
}

// round 4
// speedup vs baseline: 2.2287x; 1.9309x over previous
#include <cuda_runtime.h>
#include <math.h>

#define HOPSZ 512
#define MAX_NHAR 128
#define NWPAD 4416              // >= max winsize 4410, multiple of 8

// angle = (float)(int64)(q) * PH  maps Q64 phase-fraction to wrapped radians in [-pi, pi)
#define PH 3.4061215800872442e-19f   // 2*pi / 2^64

__global__ __launch_bounds__(256) void czt_q64_kernel(
    const float* __restrict__ x,
    const float* __restrict__ f0g,
    float* __restrict__ out,
    int T, int nframes)
{
    __shared__ __align__(16) float xw[NWPAD];
    __shared__ float red_r[256], red_i[256];
    __shared__ unsigned long long phi_q_s;
    __shared__ int nhar_s, winsize_s;

    const int frame = blockIdx.x;
    const int tid = threadIdx.x;

    // ---- one thread: the only fp64 in the kernel (exact reference semantics) ----
    if (tid == 0) {
        double f0 = (double)f0g[frame];
        if (f0 < 40.0) f0 = 40.0;
        double r = 44100.0 / f0;
        int nh = (int)floor(r * 0.5);
        if (nh > MAX_NHAR) nh = MAX_NHAR;
        int ws = 2 * (int)rint(r * 2.0);            // round-half-even, matches jnp.round
        if (ws > 4410) ws = 4410;
        nhar_s = nh;
        winsize_s = ws;
        // phase fraction per sample, Q64: f0/SR * 2^64
        phi_q_s = (unsigned long long)__double2ll_rn((f0 / 44100.0) * 18446744073709551616.0);
    }
    __syncthreads();

    const int nhar = nhar_s;
    const int winsize = winsize_s;
    const unsigned long long phi_q = phi_q_s;

    // ---- phase 1: windowed frame -> smem, zero-padded to multiple of 8 ----
    const int base = frame * HOPSZ - (winsize >> 1);
    const float invn = 1.0f / (float)winsize;
    const int wsz8 = (winsize + 7) & ~7;
    for (int j = tid; j < wsz8; j += 256) {
        float v = 0.0f;
        if (j < winsize) {
            int gi = base + j;
            float xv = (gi >= 0 && gi < T) ? x[gi] : 0.0f;
            float a = 6.28318530717958647692f * ((float)j * invn);
            float w = 0.42f - 0.5f * __cosf(a) + 0.08f * __cosf(2.0f * a);
            v = xv * w;
        }
        xw[j] = v;
    }
    __syncthreads();

    // ---- phase 2: thread = (harmonic k, half-segment) ----
    const int k = tid & (MAX_NHAR - 1);
    const int seg = tid >> 7;                 // warp-uniform

    float accr = 0.0f, acci = 0.0f;

    if (k < nhar) {
        // per-harmonic Q64 step: om_q = phase fraction per sample for bin k (mod 1 automatic)
        const unsigned long long om_q = phi_q * (unsigned long long)(k + 1);

        // twiddles u_d = e^{-i om d}, d=1..7, from exact wrapped angles
        float cc1, cc2, cc3, cc4, cc5, cc6, cc7;
        float ns1, ns2, ns3, ns4, ns5, ns6, ns7;
        {
            float s, c, a;
            a = (float)(long long)(om_q * 1ull) * PH; __sincosf(a, &s, &c); cc1 = c; ns1 = -s;
            a = (float)(long long)(om_q * 2ull) * PH; __sincosf(a, &s, &c); cc2 = c; ns2 = -s;
            a = (float)(long long)(om_q * 3ull) * PH; __sincosf(a, &s, &c); cc3 = c; ns3 = -s;
            a = (float)(long long)(om_q * 4ull) * PH; __sincosf(a, &s, &c); cc4 = c; ns4 = -s;
            a = (float)(long long)(om_q * 5ull) * PH; __sincosf(a, &s, &c); cc5 = c; ns5 = -s;
            a = (float)(long long)(om_q * 6ull) * PH; __sincosf(a, &s, &c); cc6 = c; ns6 = -s;
            a = (float)(long long)(om_q * 7ull) * PH; __sincosf(a, &s, &c); cc7 = c; ns7 = -s;
        }
        float w8r, w8i;
        {
            float s, c, a = (float)(long long)(om_q * 8ull) * PH;
            __sincosf(a, &s, &c);
            w8r = c; w8i = -s;
        }

        // segment range: mult-of-8 split of [0, wsz8)
        const int Lc = ((wsz8 >> 1) + 7) & ~7;
        const int a0 = seg ? Lc : 0;
        const int b0 = seg ? wsz8 : Lc;

        for (int a2 = a0; a2 < b0; a2 += 512) {    // rotor resync every 512 samples
            float wr, wi;
            {
                float s, c, a = (float)(long long)(om_q * (unsigned long long)a2) * PH;
                __sincosf(a, &s, &c);
                wr = c; wi = -s;
            }
            int bend = a2 + 512; if (bend > b0) bend = b0;
            #pragma unroll 2
            for (int j0 = a2; j0 < bend; j0 += 8) {
                float4 xa = *(const float4*)(xw + j0);
                float4 xb = *(const float4*)(xw + j0 + 4);
                // 8-sample partials (independent FMA chains)
                float pra = xa.x;
                pra = fmaf(xa.y, cc1, pra);
                pra = fmaf(xa.z, cc2, pra);
                pra = fmaf(xa.w, cc3, pra);
                float prb = xb.x * cc4;
                prb = fmaf(xb.y, cc5, prb);
                prb = fmaf(xb.z, cc6, prb);
                prb = fmaf(xb.w, cc7, prb);
                float pia = xa.y * ns1;
                pia = fmaf(xa.z, ns2, pia);
                pia = fmaf(xa.w, ns3, pia);
                float pib = xb.x * ns4;
                pib = fmaf(xb.y, ns5, pib);
                pib = fmaf(xb.z, ns6, pib);
                pib = fmaf(xb.w, ns7, pib);
                float pr = pra + prb;
                float pi = pia + pib;
                // acc += (pr + i*pi) * (wr + i*wi)
                accr = fmaf(pr, wr, accr); accr = fmaf(pi, -wi, accr);
                acci = fmaf(pr, wi, acci); acci = fmaf(pi,  wr, acci);
                // W *= W8
                float nr = fmaf(wr, w8r, -wi * w8i);
                float ni = fmaf(wr, w8i,  wi * w8r);
                wr = nr; wi = ni;
            }
        }
    }

    red_r[tid] = accr;
    red_i[tid] = acci;
    __syncthreads();

    // ---- epilogue: combine 2 segments, scale, write ampl + phase ----
    if (tid < MAX_NHAR) {
        float ampl = 0.0f, phs = 0.0f;
        if (tid < nhar) {
            float rr = red_r[tid] + red_r[tid + 128];
            float ri = red_i[tid] + red_i[tid + 128];
            float scale = 2.381f / (float)((winsize >> 1) + 1);
            float yr = rr * scale, yi = ri * scale;
            ampl = sqrtf(yr * yr + yi * yi);
            phs = atan2f(yi, yr);
        }
        out[tid * nframes + frame] = ampl;
        out[(MAX_NHAR + tid) * nframes + frame] = phs;
    }
}

extern "C" void kernel_launch(void* const* d_in, const int* in_sizes, int n_in,
                              void* d_out, int out_size) {
    const float* x  = (const float*)d_in[0];
    const float* f0 = (const float*)d_in[1];
    float* out = (float*)d_out;
    int T = in_sizes[0];
    int nframes = in_sizes[1];
    czt_q64_kernel<<<nframes, 256>>>(x, f0, out, T, nframes);
}

// round 5
// speedup vs baseline: 2.2749x; 1.0207x over previous
#include <cuda_runtime.h>
#include <math.h>

#define HOPSZ 512
#define MAX_NHAR 128
#define NWPAD 4416              // >= max winsize 4410, multiple of 16
#define PH 3.4061215800872442e-19f   // 2*pi / 2^64

typedef unsigned long long ull;

__forceinline__ __device__ ull pk2(float lo, float hi) {
    ull r; asm("mov.b64 %0, {%1,%2};" : "=l"(r) : "f"(lo), "f"(hi)); return r;
}
__forceinline__ __device__ ull fma2(ull a, ull b, ull c) {
    ull d; asm("fma.rn.f32x2 %0, %1, %2, %3;" : "=l"(d) : "l"(a), "l"(b), "l"(c)); return d;
}
__forceinline__ __device__ ull mul2(ull a, ull b) {
    ull d; asm("mul.rn.f32x2 %0, %1, %2;" : "=l"(d) : "l"(a), "l"(b)); return d;
}
__forceinline__ __device__ float hadd2(ull v) {
    float lo, hi; asm("mov.b64 {%0,%1}, %2;" : "=f"(lo), "=f"(hi) : "l"(v)); return lo + hi;
}

__global__ __launch_bounds__(256) void czt_q64_pk_kernel(
    const float* __restrict__ x,
    const float* __restrict__ f0g,
    float* __restrict__ out,
    int T, int nframes)
{
    __shared__ __align__(16) float xw[NWPAD];
    __shared__ float red_r[256], red_i[256];
    __shared__ ull phi_q_s;
    __shared__ int nhar_s, winsize_s;

    const int frame = blockIdx.x;
    const int tid = threadIdx.x;

    // ---- only fp64 in the kernel: exact reference scalar semantics ----
    if (tid == 0) {
        double f0 = (double)f0g[frame];
        if (f0 < 40.0) f0 = 40.0;
        double r = 44100.0 / f0;
        int nh = (int)floor(r * 0.5);
        if (nh > MAX_NHAR) nh = MAX_NHAR;
        if (nh < 1) nh = 1;
        int ws = 2 * (int)rint(r * 2.0);
        if (ws > 4410) ws = 4410;
        nhar_s = nh;
        winsize_s = ws;
        phi_q_s = (ull)__double2ll_rn((f0 / 44100.0) * 18446744073709551616.0);
    }
    __syncthreads();

    const int nhar = nhar_s;
    const int winsize = winsize_s;
    const ull phi_q = phi_q_s;

    // ---- phase 1: windowed frame -> smem, zero-padded to multiple of 16 ----
    const int base = frame * HOPSZ - (winsize >> 1);
    const float invn = 1.0f / (float)winsize;
    const int wsz16 = (winsize + 15) & ~15;
    for (int j = tid; j < wsz16; j += 256) {
        float v = 0.0f;
        if (j < winsize) {
            int gi = base + j;
            float xv = (gi >= 0 && gi < T) ? x[gi] : 0.0f;
            float a = 6.28318530717958647692f * ((float)j * invn);
            float w = 0.42f - 0.5f * __cosf(a) + 0.08f * __cosf(2.0f * a);
            v = xv * w;
        }
        xw[j] = v;
    }
    __syncthreads();

    // ---- balanced (k, segment) mapping: all 256 threads active ----
    const int k = tid % nhar;
    const int s = tid / nhar;
    const int nsegk = (255 - k) / nhar + 1;

    // per-harmonic Q64 phase step
    const ull om_q = phi_q * (ull)(k + 1);

    // twiddles u_d = e^{-i om d}, d=0..15, packed in pairs
    float ccv[16], nsv[16];
    ccv[0] = 1.0f; nsv[0] = 0.0f;
    #pragma unroll
    for (int d = 1; d < 16; ++d) {
        float a = (float)(long long)(om_q * (ull)d) * PH;
        float sn, cs; __sincosf(a, &sn, &cs);
        ccv[d] = cs; nsv[d] = -sn;
    }
    ull C0 = pk2(ccv[0], ccv[1]),  C1 = pk2(ccv[2], ccv[3]);
    ull C2 = pk2(ccv[4], ccv[5]),  C3 = pk2(ccv[6], ccv[7]);
    ull C4 = pk2(ccv[8], ccv[9]),  C5 = pk2(ccv[10], ccv[11]);
    ull C6 = pk2(ccv[12], ccv[13]), C7 = pk2(ccv[14], ccv[15]);
    ull S0 = pk2(nsv[0], nsv[1]),  S1 = pk2(nsv[2], nsv[3]);
    ull S2 = pk2(nsv[4], nsv[5]),  S3 = pk2(nsv[6], nsv[7]);
    ull S4 = pk2(nsv[8], nsv[9]),  S5 = pk2(nsv[10], nsv[11]);
    ull S6 = pk2(nsv[12], nsv[13]), S7 = pk2(nsv[14], nsv[15]);

    float w16r, w16i;
    {
        float a = (float)(long long)(om_q * 16ull) * PH;
        float sn, cs; __sincosf(a, &sn, &cs);
        w16r = cs; w16i = -sn;
    }

    // segment bounds (multiples of 16)
    const int Lc = (((wsz16 + nsegk - 1) / nsegk) + 15) & ~15;
    int a0 = s * Lc;
    int b0 = a0 + Lc; if (b0 > wsz16) b0 = wsz16;

    float accr = 0.0f, acci = 0.0f;

    for (int a2 = a0; a2 < b0; a2 += 512) {          // exact rotor resync
        float wr, wi;
        {
            float a = (float)(long long)(om_q * (ull)a2) * PH;
            float sn, cs; __sincosf(a, &sn, &cs);
            wr = cs; wi = -sn;
        }
        int bend = a2 + 512; if (bend > b0) bend = b0;
        #pragma unroll 2
        for (int j0 = a2; j0 < bend; j0 += 16) {
            ulonglong2 qa = *(const ulonglong2*)(xw + j0);
            ulonglong2 qb = *(const ulonglong2*)(xw + j0 + 4);
            ulonglong2 qc = *(const ulonglong2*)(xw + j0 + 8);
            ulonglong2 qd = *(const ulonglong2*)(xw + j0 + 12);
            // packed partials over 16 samples
            ull mr = mul2(qa.x, C0);
            mr = fma2(qa.y, C1, mr);
            mr = fma2(qb.x, C2, mr);
            mr = fma2(qb.y, C3, mr);
            mr = fma2(qc.x, C4, mr);
            mr = fma2(qc.y, C5, mr);
            mr = fma2(qd.x, C6, mr);
            mr = fma2(qd.y, C7, mr);
            ull mi = mul2(qa.x, S0);
            mi = fma2(qa.y, S1, mi);
            mi = fma2(qb.x, S2, mi);
            mi = fma2(qb.y, S3, mi);
            mi = fma2(qc.x, S4, mi);
            mi = fma2(qc.y, S5, mi);
            mi = fma2(qd.x, S6, mi);
            mi = fma2(qd.y, S7, mi);
            float pr = hadd2(mr);
            float pi = hadd2(mi);
            // acc += (pr + i*pi) * (wr + i*wi)
            accr = fmaf(pr, wr, accr); accr = fmaf(-pi, wi, accr);
            acci = fmaf(pr, wi, acci); acci = fmaf( pi, wr, acci);
            // W *= W16
            float nr = fmaf(wr, w16r, -(wi * w16i));
            float ni = fmaf(wr, w16i,   wi * w16r);
            wr = nr; wi = ni;
        }
    }

    red_r[tid] = accr;
    red_i[tid] = acci;
    __syncthreads();

    // ---- epilogue: gather segments per harmonic, scale, write ----
    if (tid < nhar) {
        float rr = 0.0f, ri = 0.0f;
        for (int u = tid; u < 256; u += nhar) { rr += red_r[u]; ri += red_i[u]; }
        float scale = 2.381f / (float)((winsize >> 1) + 1);
        float yr = rr * scale, yi = ri * scale;
        out[tid * nframes + frame] = sqrtf(yr * yr + yi * yi);
        out[(MAX_NHAR + tid) * nframes + frame] = atan2f(yi, yr);
    } else if (tid < MAX_NHAR) {
        out[tid * nframes + frame] = 0.0f;
        out[(MAX_NHAR + tid) * nframes + frame] = 0.0f;
    }
}

extern "C" void kernel_launch(void* const* d_in, const int* in_sizes, int n_in,
                              void* d_out, int out_size) {
    const float* x  = (const float*)d_in[0];
    const float* f0 = (const float*)d_in[1];
    float* out = (float*)d_out;
    int T = in_sizes[0];
    int nframes = in_sizes[1];
    czt_q64_pk_kernel<<<nframes, 256>>>(x, f0, out, T, nframes);
}